// round 8
// baseline (speedup 1.0000x reference)
#include <cuda_runtime.h>
#include <cstdint>
#include <cstddef>

#define DFF     11008
#define DMODEL  4096
#define SEQ     2048
#define MROWS   2049
#define KTOK    2201
#define KCORE   2201
#define NSPLIT  2201
#define TARGET  4403
#define NREM    (DFF - NSPLIT)

// ---- GEMM tiling ----
#define BM 128
#define BN 128
#define BK 32
#define KTILES (DFF / BK)          // 344
#define STAGES 3
#define ASTG  (BM * BK * 4)        // 16384
#define BSTG  (BN * BK * 4)        // 16384
#define STGB  (ASTG + BSTG)        // 32768
#define GEMM_SMEM (STAGES * STGB)  // 98304 -> 2 CTAs/SM

// ---------------- device scratch ----------------
__device__ __align__(16) float g_X[(size_t)SEQ * DFF];     // tf32-rounded X
__device__ __align__(16) float g_W[(size_t)DMODEL * DFF];  // tf32-rounded W
__device__ __align__(16) float g_v[DFF];
__device__ __align__(16) float g_zero[DFF];                // stays zero
__device__ int g_counts[DFF];

// ---------------- helpers ----------------
__device__ __forceinline__ unsigned fkey(float f) {
    unsigned u = __float_as_uint(f);
    return (u & 0x80000000u) ? ~u : (u | 0x80000000u);
}
__device__ __forceinline__ unsigned to_tf32(float f) {
    unsigned r;
    asm("cvt.rna.tf32.f32 %0, %1;" : "=r"(r) : "f"(f));
    return r;
}
__device__ __forceinline__ uint32_t smem_u32(const void* p) {
    uint32_t a;
    asm("{ .reg .u64 t; cvta.to.shared.u64 t, %1; cvt.u32.u64 %0, t; }" : "=r"(a) : "l"(p));
    return a;
}
__device__ __forceinline__ void cp16(uint32_t dst, const void* src) {
    asm volatile("cp.async.cg.shared.global [%0], [%1], 16;\n" :: "r"(dst), "l"(src) : "memory");
}
#define CP_COMMIT() asm volatile("cp.async.commit_group;\n" ::: "memory")
#define CP_WAIT(N)  asm volatile("cp.async.wait_group %0;\n" :: "n"(N) : "memory")

__device__ __forceinline__ void mma_tf32(float c[4],
    unsigned a0, unsigned a1, unsigned a2, unsigned a3, unsigned b0, unsigned b1)
{
    asm volatile(
        "mma.sync.aligned.m16n8k8.row.col.f32.tf32.tf32.f32 "
        "{%0,%1,%2,%3}, {%4,%5,%6,%7}, {%8,%9}, {%0,%1,%2,%3};\n"
        : "+f"(c[0]), "+f"(c[1]), "+f"(c[2]), "+f"(c[3])
        : "r"(a0), "r"(a1), "r"(a2), "r"(a3), "r"(b0), "r"(b1));
}
__device__ __forceinline__ unsigned ldsw(uint32_t base, int r, int c) {
    unsigned v;
    uint32_t a = base + (uint32_t)(r * 128) + (uint32_t)((c * 4) ^ ((r & 7) << 4));
    asm("ld.shared.b32 %0, [%1];" : "=r"(v) : "r"(a));
    return v;
}

// ---------------- kernel 0: zero scratch ----------------
__global__ void zero_misc_kernel() {
    int i = blockIdx.x * blockDim.x + threadIdx.x;
    if (i < DFF) { g_counts[i] = 0; g_v[i] = 0.0f; }
}

// ---------------- convert W: fp32 -> tf32(rna) copy ----------------
__global__ void convertW_kernel(const float4* __restrict__ src) {
    int i = blockIdx.x * blockDim.x + threadIdx.x;
    if (i < (DMODEL * DFF) / 4) {
        float4 v = src[i];
        v.x = __uint_as_float(to_tf32(v.x));
        v.y = __uint_as_float(to_tf32(v.y));
        v.z = __uint_as_float(to_tf32(v.z));
        v.w = __uint_as_float(to_tf32(v.w));
        ((float4*)g_W)[i] = v;
    }
}

// ---------------- kernel 1: per-token top-KTOK (register radix select) ----------
// Also writes the tf32-rounded row into g_X (fused convert).
#define NITER (DFF / 256)   // 43
__global__ __launch_bounds__(256) void topk_count_kernel(const float* __restrict__ x) {
    const float* row = x + (size_t)blockIdx.x * DFF;
    float* grow = g_X + (size_t)blockIdx.x * DFF;
    const int tid = threadIdx.x;
    const int lane = tid & 31, warp = tid >> 5;
    __shared__ int s_w[8];
    __shared__ int s_base;

    unsigned key[NITER];
    #pragma unroll
    for (int j = 0; j < NITER; ++j) {
        float f = row[tid + 256 * j];
        key[j] = fkey(f);
        grow[tid + 256 * j] = __uint_as_float(to_tf32(f));
    }

    unsigned p = 0;
    for (int b = 31; b >= 0; --b) {
        unsigned cand = p | (1u << b);
        int loc = 0;
        #pragma unroll
        for (int j = 0; j < NITER; ++j) loc += (key[j] >= cand);
        #pragma unroll
        for (int o = 16; o; o >>= 1) loc += __shfl_down_sync(0xffffffffu, loc, o);
        __syncthreads();
        if (lane == 0) s_w[warp] = loc;
        __syncthreads();
        int tot = 0;
        #pragma unroll
        for (int w = 0; w < 8; ++w) tot += s_w[w];
        if (tot >= KTOK) p = cand;
    }

    {
        int loc = 0;
        #pragma unroll
        for (int j = 0; j < NITER; ++j) loc += (key[j] > p);
        #pragma unroll
        for (int o = 16; o; o >>= 1) loc += __shfl_down_sync(0xffffffffu, loc, o);
        __syncthreads();
        if (lane == 0) s_w[warp] = loc;
        __syncthreads();
    }
    int cgt = 0;
    #pragma unroll
    for (int w = 0; w < 8; ++w) cgt += s_w[w];
    const int need = KTOK - cgt;

    #pragma unroll
    for (int j = 0; j < NITER; ++j)
        if (key[j] > p) atomicAdd(&g_counts[tid + 256 * j], 1);

    if (tid == 0) s_base = 0;
    __syncthreads();
    for (int j = 0; j < NITER; ++j) {
        int eq = (key[j] == p);
        unsigned bal = __ballot_sync(0xffffffffu, eq);
        if (lane == 0) s_w[warp] = __popc(bal);
        __syncthreads();
        int woff = 0;
        for (int w = 0; w < warp; ++w) woff += s_w[w];
        int tot = 0;
        #pragma unroll
        for (int w = 0; w < 8; ++w) tot += s_w[w];
        if (eq) {
            int r = s_base + woff + __popc(bal & ((1u << lane) - 1u));
            if (r < need) atomicAdd(&g_counts[tid + 256 * j], 1);
        }
        __syncthreads();
        if (tid == 0) s_base += tot;
        __syncthreads();
    }
}

// ---------------- kernel 2: core selection + union + build v ----------------
__device__ __forceinline__ int blockScanBit(int flag, int tid, unsigned* wsum, int* tot) {
    int lane = tid & 31, w = tid >> 5;
    unsigned b = __ballot_sync(0xffffffffu, flag);
    int pre = __popc(b & ((1u << lane) - 1u));
    if (lane == 0) wsum[w] = __popc(b);
    __syncthreads();
    if (w == 0) {
        int v = (int)wsum[lane];
        #pragma unroll
        for (int o = 1; o < 32; o <<= 1) {
            int n = __shfl_up_sync(0xffffffffu, v, o);
            if (lane >= o) v += n;
        }
        wsum[lane] = (unsigned)v;
    }
    __syncthreads();
    int off = w ? (int)wsum[w - 1] : 0;
    *tot = (int)wsum[31];
    int r = off + pre;
    __syncthreads();
    return r;
}

// inclusive block scan (add) over 1024 threads
__device__ __forceinline__ int blockScanAddInc(int v, int tid, int* wsum32) {
    int lane = tid & 31, w = tid >> 5;
    #pragma unroll
    for (int o = 1; o < 32; o <<= 1) {
        int n = __shfl_up_sync(0xffffffffu, v, o);
        if (lane >= o) v += n;
    }
    if (lane == 31) wsum32[w] = v;
    __syncthreads();
    if (w == 0) {
        int s = wsum32[lane];
        #pragma unroll
        for (int o = 1; o < 32; o <<= 1) {
            int n = __shfl_up_sync(0xffffffffu, s, o);
            if (lane >= o) s += n;
        }
        wsum32[lane] = s;
    }
    __syncthreads();
    int off = w ? wsum32[w - 1] : 0;
    int r = v + off;
    __syncthreads();
    return r;
}

__global__ __launch_bounds__(1024) void select_build_v_kernel(
    const int* __restrict__ mneur, const float* __restrict__ xdec)
{
    __shared__ int hist[2049];
    __shared__ unsigned wsum[32];
    __shared__ int iwsum[32];
    __shared__ unsigned maskw[(DFF + 31) / 32];
    __shared__ int s_cstar, s_need, s_carry, s_U;

    const int tid = threadIdx.x;
    for (int i = tid; i < 2049; i += 1024) hist[i] = 0;
    for (int i = tid; i < (DFF + 31) / 32; i += 1024) maskw[i] = 0u;
    __syncthreads();

    for (int i = tid; i < DFF; i += 1024) atomicAdd(&hist[g_counts[i]], 1);
    __syncthreads();

    // parallel suffix threshold: reversed array idx i -> bin c = 2048 - i
    {
        int e0 = hist[2048 - (2 * tid)];
        int e1 = hist[2048 - (2 * tid + 1)];
        int inc = blockScanAddInc(e0 + e1, tid, iwsum);
        int P1 = inc;
        int P0 = inc - e1;
        int Pm1 = P0 - e0;
        if (P0 >= KCORE && Pm1 < KCORE) { s_cstar = 2048 - 2 * tid; s_need = KCORE - Pm1; }
        if (P1 >= KCORE && P0  < KCORE) { s_cstar = 2048 - (2 * tid + 1); s_need = KCORE - P0; }
        if (tid == 1023 && P1 < KCORE)  { s_cstar = 0; s_need = KCORE - P1; }
        if (tid == 0) s_carry = 0;
    }
    __syncthreads();

    for (int j = tid; j < NSPLIT; j += 1024) {
        int n = mneur[j];
        atomicOr(&maskw[n >> 5], 1u << (n & 31));
    }
    const int cs = s_cstar, need = s_need;
    __syncthreads();

    for (int base = 0; base < DFF; base += 1024) {
        int i = base + tid;
        int cnt = (i < DFF) ? g_counts[i] : -1;
        int eq = (cnt == cs);
        int tot;
        int pre = blockScanBit(eq, tid, wsum, &tot);
        int take = eq && (s_carry + pre) < need;
        if ((cnt > cs) || take) atomicOr(&maskw[i >> 5], 1u << (i & 31));
        __syncthreads();
        if (tid == 0) s_carry += tot;
        __syncthreads();
    }

    if (tid == 0) s_carry = 0;
    __syncthreads();
    for (int base = 0; base < DFF; base += 1024) {
        int i = base + tid;
        int fl = (i < DFF) && ((maskw[i >> 5] >> (i & 31)) & 1u);
        int tot;
        int pre = blockScanBit(fl, tid, wsum, &tot);
        if (fl) g_v[i] = xdec[s_carry + pre];
        __syncthreads();
        if (tid == 0) s_carry += tot;
        __syncthreads();
    }
    if (tid == 0) { s_U = s_carry; s_carry = 0; }
    __syncthreads();
    const int U = s_U;
    const int R = TARGET - U;

    for (int base = 0; base < NREM; base += 1024) {
        int j = base + tid;
        int nj = (j < NREM) ? mneur[NSPLIT + j] : 0;
        int fl = (j < NREM) && !((maskw[nj >> 5] >> (nj & 31)) & 1u);
        int tot;
        int pre = blockScanBit(fl, tid, wsum, &tot);
        int pos = s_carry + pre;
        if (fl && pos < R) g_v[nj] = xdec[U + pos];
        __syncthreads();
        if (tid == 0) s_carry += tot;
        __syncthreads();
    }
}

// ---------------- kernel 3: TF32 mma.sync GEMM, 128x128, 3-stage, 2 CTAs/SM ----
// out(2049x4096) = X'(2049x11008) @ W^T. 8 warps, 64x32 warp tiles.
__global__ __launch_bounds__(256, 2) void gemm_mma_kernel(float* __restrict__ out)
{
    extern __shared__ char smem[];
    const uint32_t sb = smem_u32(smem);
    const int tid  = threadIdx.x;
    const int lane = tid & 31;
    const int warp = tid >> 5;
    const int gid  = lane >> 2;      // 0..7
    const int tig  = lane & 3;       // 0..3
    const int wm   = (warp & 1) * 64;
    const int wn   = (warp >> 1) * 32;
    const int m0   = blockIdx.x * BM;
    const int n0   = blockIdx.y * BN;

    const int cc = tid & 7;          // 16B chunk in 128B row
    const int rb = tid >> 3;         // 0..31
    const float* aSrc[4];
    #pragma unroll
    for (int p = 0; p < 4; ++p) {
        int m = m0 + rb + 32 * p;
        aSrc[p] = (m < SEQ) ? (g_X + (size_t)m * DFF + cc * 4)
                 : (m == SEQ ? (g_v + cc * 4) : (g_zero + cc * 4));
    }
    const float* bSrc = g_W + (size_t)(n0 + rb) * DFF + cc * 4;
    const uint32_t swo = (uint32_t)((cc * 16) ^ ((rb & 7) << 4));

    auto load_stage = [&](int s, int kt) {
        uint32_t ab = sb + s * STGB;
        uint32_t bb = ab + ASTG;
        #pragma unroll
        for (int p = 0; p < 4; ++p)
            cp16(ab + (uint32_t)((rb + 32 * p) * 128) + swo, aSrc[p] + (size_t)kt * BK);
        #pragma unroll
        for (int p = 0; p < 4; ++p)
            cp16(bb + (uint32_t)((rb + 32 * p) * 128) + swo, bSrc + (size_t)p * 32 * DFF + (size_t)kt * BK);
    };

    float acc[4][4][4];
    #pragma unroll
    for (int mt = 0; mt < 4; ++mt)
        #pragma unroll
        for (int nt = 0; nt < 4; ++nt)
            #pragma unroll
            for (int q = 0; q < 4; ++q) acc[mt][nt][q] = 0.0f;

    #pragma unroll
    for (int s = 0; s < STAGES - 1; ++s) { load_stage(s, s); CP_COMMIT(); }

    #pragma unroll 1
    for (int kt = 0; kt < KTILES; ++kt) {
        CP_WAIT(STAGES - 2);
        __syncthreads();

        if (kt + STAGES - 1 < KTILES) {
            int s = (kt + STAGES - 1) % STAGES;
            load_stage(s, kt + STAGES - 1);
        }
        CP_COMMIT();

        const uint32_t ab = sb + (kt % STAGES) * STGB;
        const uint32_t bb = ab + ASTG;

        #pragma unroll
        for (int ks = 0; ks < 4; ++ks) {
            const int kb = ks * 8;
            unsigned a[4][4], b[4][2];
            #pragma unroll
            for (int mt = 0; mt < 4; ++mt) {
                int r = wm + mt * 16 + gid;
                a[mt][0] = ldsw(ab, r,     kb + tig);
                a[mt][1] = ldsw(ab, r + 8, kb + tig);
                a[mt][2] = ldsw(ab, r,     kb + tig + 4);
                a[mt][3] = ldsw(ab, r + 8, kb + tig + 4);
            }
            #pragma unroll
            for (int nt = 0; nt < 4; ++nt) {
                int c = wn + nt * 8 + gid;
                b[nt][0] = ldsw(bb, c, kb + tig);
                b[nt][1] = ldsw(bb, c, kb + tig + 4);
            }
            #pragma unroll
            for (int mt = 0; mt < 4; ++mt)
                #pragma unroll
                for (int nt = 0; nt < 4; ++nt)
                    mma_tf32(acc[mt][nt], a[mt][0], a[mt][1], a[mt][2], a[mt][3],
                             b[nt][0], b[nt][1]);
        }
    }

    // epilogue: plain stores with row guard
    #pragma unroll
    for (int mt = 0; mt < 4; ++mt) {
        int r0 = m0 + wm + mt * 16 + gid;
        #pragma unroll
        for (int nt = 0; nt < 4; ++nt) {
            int c = n0 + wn + nt * 8 + tig * 2;
            if (r0 < MROWS)
                *(float2*)(out + (size_t)r0 * DMODEL + c) = make_float2(acc[mt][nt][0], acc[mt][nt][1]);
            if (r0 + 8 < MROWS)
                *(float2*)(out + (size_t)(r0 + 8) * DMODEL + c) = make_float2(acc[mt][nt][2], acc[mt][nt][3]);
        }
    }
}

// ---------------- launcher ----------------
extern "C" void kernel_launch(void* const* d_in, const int* in_sizes, int n_in,
                              void* d_out, int out_size) {
    const float* x    = (const float*)d_in[0];
    const float* W    = (const float*)d_in[1];
    const float* xdec = (const float*)d_in[2];
    const int*   mn   = (const int*)d_in[3];
    float* out = (float*)d_out;

    zero_misc_kernel<<<(DFF + 255) / 256, 256>>>();
    convertW_kernel<<<((DMODEL * DFF / 4) + 255) / 256, 256>>>((const float4*)W);
    topk_count_kernel<<<SEQ, 256>>>(x);
    select_build_v_kernel<<<1, 1024>>>(mn, xdec);

    cudaFuncSetAttribute(gemm_mma_kernel, cudaFuncAttributeMaxDynamicSharedMemorySize, GEMM_SMEM);
    dim3 grid((MROWS + BM - 1) / BM, DMODEL / BN);   // (17, 32)
    gemm_mma_kernel<<<grid, 256, GEMM_SMEM>>>(out);
}

// round 9
// speedup vs baseline: 1.0290x; 1.0290x over previous
#include <cuda_runtime.h>
#include <cstdint>
#include <cstddef>

#define DFF     11008
#define DMODEL  4096
#define SEQ     2048
#define MROWS   2049
#define KTOK    2201
#define KCORE   2201
#define NSPLIT  2201
#define TARGET  4403
#define NREM    (DFF - NSPLIT)

// ---- GEMM tiling ----
#define BM 128
#define BN 256
#define BK 32
#define KTILES (DFF / BK)          // 344
#define STAGES 4
#define ASTG  (BM * BK * 4)        // 16384
#define BSTG  (BN * BK * 4)        // 32768
#define STGB  (ASTG + BSTG)        // 49152
#define GEMM_SMEM (STAGES * STGB)  // 196608, 1 CTA/SM

// ---------------- device scratch ----------------
__device__ __align__(16) float g_X[(size_t)SEQ * DFF];     // tf32-rounded X
__device__ __align__(16) float g_W[(size_t)DMODEL * DFF];  // tf32-rounded W
__device__ __align__(16) float g_v[DFF];
__device__ __align__(16) float g_zero[DFF];                // stays zero
__device__ int g_counts[DFF];

// ---------------- helpers ----------------
__device__ __forceinline__ unsigned fkey(float f) {
    unsigned u = __float_as_uint(f);
    return (u & 0x80000000u) ? ~u : (u | 0x80000000u);
}
__device__ __forceinline__ unsigned to_tf32(float f) {
    unsigned r;
    asm("cvt.rna.tf32.f32 %0, %1;" : "=r"(r) : "f"(f));
    return r;
}
__device__ __forceinline__ uint32_t smem_u32(const void* p) {
    uint32_t a;
    asm("{ .reg .u64 t; cvta.to.shared.u64 t, %1; cvt.u32.u64 %0, t; }" : "=r"(a) : "l"(p));
    return a;
}
__device__ __forceinline__ void cp16(uint32_t dst, const void* src) {
    asm volatile("cp.async.cg.shared.global [%0], [%1], 16;\n" :: "r"(dst), "l"(src) : "memory");
}
#define CP_COMMIT() asm volatile("cp.async.commit_group;\n" ::: "memory")
#define CP_WAIT(N)  asm volatile("cp.async.wait_group %0;\n" :: "n"(N) : "memory")

__device__ __forceinline__ void mma_tf32(float c[4],
    unsigned a0, unsigned a1, unsigned a2, unsigned a3, unsigned b0, unsigned b1)
{
    asm volatile(
        "mma.sync.aligned.m16n8k8.row.col.f32.tf32.tf32.f32 "
        "{%0,%1,%2,%3}, {%4,%5,%6,%7}, {%8,%9}, {%0,%1,%2,%3};\n"
        : "+f"(c[0]), "+f"(c[1]), "+f"(c[2]), "+f"(c[3])
        : "r"(a0), "r"(a1), "r"(a2), "r"(a3), "r"(b0), "r"(b1));
}
__device__ __forceinline__ unsigned ldsw(uint32_t base, int r, int c) {
    unsigned v;
    uint32_t a = base + (uint32_t)(r * 128) + (uint32_t)((c * 4) ^ ((r & 7) << 4));
    asm("ld.shared.b32 %0, [%1];" : "=r"(v) : "r"(a));
    return v;
}

// ---------------- kernel A: convert W (rna->tf32) + zero scratch (fused) ------
__global__ void convertW_zero_kernel(const float4* __restrict__ src) {
    int i = blockIdx.x * blockDim.x + threadIdx.x;
    if (i < DFF) { g_counts[i] = 0; g_v[i] = 0.0f; }
    if (i < (DMODEL * DFF) / 4) {
        float4 v = src[i];
        v.x = __uint_as_float(to_tf32(v.x));
        v.y = __uint_as_float(to_tf32(v.y));
        v.z = __uint_as_float(to_tf32(v.z));
        v.w = __uint_as_float(to_tf32(v.w));
        ((float4*)g_W)[i] = v;
    }
}

// ---------------- kernel B: per-token top-KTOK (register radix select) --------
// Also writes the tf32-rounded row into g_X (fused convert).
#define NITER (DFF / 256)   // 43
__global__ __launch_bounds__(256) void topk_count_kernel(const float* __restrict__ x) {
    const float* row = x + (size_t)blockIdx.x * DFF;
    float* grow = g_X + (size_t)blockIdx.x * DFF;
    const int tid = threadIdx.x;
    const int lane = tid & 31, warp = tid >> 5;
    __shared__ int s_w[8];
    __shared__ int s_base;

    unsigned key[NITER];
    #pragma unroll
    for (int j = 0; j < NITER; ++j) {
        float f = row[tid + 256 * j];
        key[j] = fkey(f);
        grow[tid + 256 * j] = __uint_as_float(to_tf32(f));
    }

    unsigned p = 0;
    for (int b = 31; b >= 0; --b) {
        unsigned cand = p | (1u << b);
        int loc = 0;
        #pragma unroll
        for (int j = 0; j < NITER; ++j) loc += (key[j] >= cand);
        #pragma unroll
        for (int o = 16; o; o >>= 1) loc += __shfl_down_sync(0xffffffffu, loc, o);
        __syncthreads();
        if (lane == 0) s_w[warp] = loc;
        __syncthreads();
        int tot = 0;
        #pragma unroll
        for (int w = 0; w < 8; ++w) tot += s_w[w];
        if (tot >= KTOK) p = cand;
    }

    {
        int loc = 0;
        #pragma unroll
        for (int j = 0; j < NITER; ++j) loc += (key[j] > p);
        #pragma unroll
        for (int o = 16; o; o >>= 1) loc += __shfl_down_sync(0xffffffffu, loc, o);
        __syncthreads();
        if (lane == 0) s_w[warp] = loc;
        __syncthreads();
    }
    int cgt = 0;
    #pragma unroll
    for (int w = 0; w < 8; ++w) cgt += s_w[w];
    const int need = KTOK - cgt;

    #pragma unroll
    for (int j = 0; j < NITER; ++j)
        if (key[j] > p) atomicAdd(&g_counts[tid + 256 * j], 1);

    if (tid == 0) s_base = 0;
    __syncthreads();
    for (int j = 0; j < NITER; ++j) {
        int eq = (key[j] == p);
        unsigned bal = __ballot_sync(0xffffffffu, eq);
        if (lane == 0) s_w[warp] = __popc(bal);
        __syncthreads();
        int woff = 0;
        for (int w = 0; w < warp; ++w) woff += s_w[w];
        int tot = 0;
        #pragma unroll
        for (int w = 0; w < 8; ++w) tot += s_w[w];
        if (eq) {
            int r = s_base + woff + __popc(bal & ((1u << lane) - 1u));
            if (r < need) atomicAdd(&g_counts[tid + 256 * j], 1);
        }
        __syncthreads();
        if (tid == 0) s_base += tot;
        __syncthreads();
    }
}

// ---------------- kernel C: core selection + union + build v ----------------
__device__ __forceinline__ int blockScanBit(int flag, int tid, unsigned* wsum, int* tot) {
    int lane = tid & 31, w = tid >> 5;
    unsigned b = __ballot_sync(0xffffffffu, flag);
    int pre = __popc(b & ((1u << lane) - 1u));
    if (lane == 0) wsum[w] = __popc(b);
    __syncthreads();
    if (w == 0) {
        int v = (int)wsum[lane];
        #pragma unroll
        for (int o = 1; o < 32; o <<= 1) {
            int n = __shfl_up_sync(0xffffffffu, v, o);
            if (lane >= o) v += n;
        }
        wsum[lane] = (unsigned)v;
    }
    __syncthreads();
    int off = w ? (int)wsum[w - 1] : 0;
    *tot = (int)wsum[31];
    int r = off + pre;
    __syncthreads();
    return r;
}

__device__ __forceinline__ int blockScanAddInc(int v, int tid, int* wsum32) {
    int lane = tid & 31, w = tid >> 5;
    #pragma unroll
    for (int o = 1; o < 32; o <<= 1) {
        int n = __shfl_up_sync(0xffffffffu, v, o);
        if (lane >= o) v += n;
    }
    if (lane == 31) wsum32[w] = v;
    __syncthreads();
    if (w == 0) {
        int s = wsum32[lane];
        #pragma unroll
        for (int o = 1; o < 32; o <<= 1) {
            int n = __shfl_up_sync(0xffffffffu, s, o);
            if (lane >= o) s += n;
        }
        wsum32[lane] = s;
    }
    __syncthreads();
    int off = w ? wsum32[w - 1] : 0;
    int r = v + off;
    __syncthreads();
    return r;
}

__global__ __launch_bounds__(1024) void select_build_v_kernel(
    const int* __restrict__ mneur, const float* __restrict__ xdec)
{
    __shared__ int hist[2049];
    __shared__ unsigned wsum[32];
    __shared__ int iwsum[32];
    __shared__ unsigned maskw[(DFF + 31) / 32];
    __shared__ int s_cstar, s_need, s_carry, s_U;

    const int tid = threadIdx.x;
    for (int i = tid; i < 2049; i += 1024) hist[i] = 0;
    for (int i = tid; i < (DFF + 31) / 32; i += 1024) maskw[i] = 0u;
    __syncthreads();

    for (int i = tid; i < DFF; i += 1024) atomicAdd(&hist[g_counts[i]], 1);
    __syncthreads();

    {
        int e0 = hist[2048 - (2 * tid)];
        int e1 = hist[2048 - (2 * tid + 1)];
        int inc = blockScanAddInc(e0 + e1, tid, iwsum);
        int P1 = inc;
        int P0 = inc - e1;
        int Pm1 = P0 - e0;
        if (P0 >= KCORE && Pm1 < KCORE) { s_cstar = 2048 - 2 * tid; s_need = KCORE - Pm1; }
        if (P1 >= KCORE && P0  < KCORE) { s_cstar = 2048 - (2 * tid + 1); s_need = KCORE - P0; }
        if (tid == 1023 && P1 < KCORE)  { s_cstar = 0; s_need = KCORE - P1; }
        if (tid == 0) s_carry = 0;
    }
    __syncthreads();

    for (int j = tid; j < NSPLIT; j += 1024) {
        int n = mneur[j];
        atomicOr(&maskw[n >> 5], 1u << (n & 31));
    }
    const int cs = s_cstar, need = s_need;
    __syncthreads();

    for (int base = 0; base < DFF; base += 1024) {
        int i = base + tid;
        int cnt = (i < DFF) ? g_counts[i] : -1;
        int eq = (cnt == cs);
        int tot;
        int pre = blockScanBit(eq, tid, wsum, &tot);
        int take = eq && (s_carry + pre) < need;
        if ((cnt > cs) || take) atomicOr(&maskw[i >> 5], 1u << (i & 31));
        __syncthreads();
        if (tid == 0) s_carry += tot;
        __syncthreads();
    }

    if (tid == 0) s_carry = 0;
    __syncthreads();
    for (int base = 0; base < DFF; base += 1024) {
        int i = base + tid;
        int fl = (i < DFF) && ((maskw[i >> 5] >> (i & 31)) & 1u);
        int tot;
        int pre = blockScanBit(fl, tid, wsum, &tot);
        if (fl) g_v[i] = xdec[s_carry + pre];
        __syncthreads();
        if (tid == 0) s_carry += tot;
        __syncthreads();
    }
    if (tid == 0) { s_U = s_carry; s_carry = 0; }
    __syncthreads();
    const int U = s_U;
    const int R = TARGET - U;

    for (int base = 0; base < NREM; base += 1024) {
        int j = base + tid;
        int nj = (j < NREM) ? mneur[NSPLIT + j] : 0;
        int fl = (j < NREM) && !((maskw[nj >> 5] >> (nj & 31)) & 1u);
        int tot;
        int pre = blockScanBit(fl, tid, wsum, &tot);
        int pos = s_carry + pre;
        if (fl && pos < R) g_v[nj] = xdec[U + pos];
        __syncthreads();
        if (tid == 0) s_carry += tot;
        __syncthreads();
    }
}

// ---------------- kernel D: TF32 mma.sync GEMM, 128x256, 512 thr, 4-stage ----
// out(2049x4096) = X'(2049x11008) @ W^T. 16 warps (4/SMSP), 64x32 warp tiles.
__global__ __launch_bounds__(512, 1) void gemm_mma_kernel(float* __restrict__ out)
{
    extern __shared__ char smem[];
    const uint32_t sb = smem_u32(smem);
    const int tid  = threadIdx.x;
    const int lane = tid & 31;
    const int warp = tid >> 5;       // 0..15
    const int gid  = lane >> 2;      // 0..7
    const int tig  = lane & 3;       // 0..3
    const int wm   = (warp & 1) * 64;        // 0,64
    const int wn   = (warp >> 1) * 32;       // 0..224
    const int m0   = blockIdx.x * BM;
    const int n0   = blockIdx.y * BN;

    // cp.async geometry: 512 threads, 6 chunks each (A:2, B:4)
    const int cc = tid & 7;          // 16B chunk in 128B row
    const int rb = tid >> 3;         // 0..63
    const float* aSrc[2];
    #pragma unroll
    for (int p = 0; p < 2; ++p) {
        int m = m0 + rb + 64 * p;
        aSrc[p] = (m < SEQ) ? (g_X + (size_t)m * DFF + cc * 4)
                 : (m == SEQ ? (g_v + cc * 4) : (g_zero + cc * 4));
    }
    const float* bSrc = g_W + (size_t)(n0 + rb) * DFF + cc * 4;
    const uint32_t swo = (uint32_t)((cc * 16) ^ ((rb & 7) << 4));

    auto load_stage = [&](int s, int kt) {
        uint32_t ab = sb + s * STGB;
        uint32_t bb = ab + ASTG;
        #pragma unroll
        for (int p = 0; p < 2; ++p)
            cp16(ab + (uint32_t)((rb + 64 * p) * 128) + swo, aSrc[p] + (size_t)kt * BK);
        #pragma unroll
        for (int q = 0; q < 4; ++q)
            cp16(bb + (uint32_t)((rb + 64 * q) * 128) + swo, bSrc + (size_t)q * 64 * DFF + (size_t)kt * BK);
    };

    float acc[4][4][4];
    #pragma unroll
    for (int mt = 0; mt < 4; ++mt)
        #pragma unroll
        for (int nt = 0; nt < 4; ++nt)
            #pragma unroll
            for (int q = 0; q < 4; ++q) acc[mt][nt][q] = 0.0f;

    #pragma unroll
    for (int s = 0; s < STAGES - 1; ++s) { load_stage(s, s); CP_COMMIT(); }

    #pragma unroll 1
    for (int kt = 0; kt < KTILES; ++kt) {
        CP_WAIT(STAGES - 2);
        __syncthreads();

        if (kt + STAGES - 1 < KTILES) {
            int s = (kt + STAGES - 1) % STAGES;
            load_stage(s, kt + STAGES - 1);
        }
        CP_COMMIT();

        const uint32_t ab = sb + (kt % STAGES) * STGB;
        const uint32_t bb = ab + ASTG;

        #pragma unroll
        for (int ks = 0; ks < 4; ++ks) {
            const int kb = ks * 8;
            unsigned a[4][4], b[4][2];
            #pragma unroll
            for (int mt = 0; mt < 4; ++mt) {
                int r = wm + mt * 16 + gid;
                a[mt][0] = ldsw(ab, r,     kb + tig);
                a[mt][1] = ldsw(ab, r + 8, kb + tig);
                a[mt][2] = ldsw(ab, r,     kb + tig + 4);
                a[mt][3] = ldsw(ab, r + 8, kb + tig + 4);
            }
            #pragma unroll
            for (int nt = 0; nt < 4; ++nt) {
                int c = wn + nt * 8 + gid;
                b[nt][0] = ldsw(bb, c, kb + tig);
                b[nt][1] = ldsw(bb, c, kb + tig + 4);
            }
            #pragma unroll
            for (int mt = 0; mt < 4; ++mt)
                #pragma unroll
                for (int nt = 0; nt < 4; ++nt)
                    mma_tf32(acc[mt][nt], a[mt][0], a[mt][1], a[mt][2], a[mt][3],
                             b[nt][0], b[nt][1]);
        }
    }

    // epilogue: plain stores with row guard
    #pragma unroll
    for (int mt = 0; mt < 4; ++mt) {
        int r0 = m0 + wm + mt * 16 + gid;
        #pragma unroll
        for (int nt = 0; nt < 4; ++nt) {
            int c = n0 + wn + nt * 8 + tig * 2;
            if (r0 < MROWS)
                *(float2*)(out + (size_t)r0 * DMODEL + c) = make_float2(acc[mt][nt][0], acc[mt][nt][1]);
            if (r0 + 8 < MROWS)
                *(float2*)(out + (size_t)(r0 + 8) * DMODEL + c) = make_float2(acc[mt][nt][2], acc[mt][nt][3]);
        }
    }
}

// ---------------- launcher ----------------
extern "C" void kernel_launch(void* const* d_in, const int* in_sizes, int n_in,
                              void* d_out, int out_size) {
    const float* x    = (const float*)d_in[0];
    const float* W    = (const float*)d_in[1];
    const float* xdec = (const float*)d_in[2];
    const int*   mn   = (const int*)d_in[3];
    float* out = (float*)d_out;

    convertW_zero_kernel<<<((DMODEL * DFF / 4) + 255) / 256, 256>>>((const float4*)W);
    topk_count_kernel<<<SEQ, 256>>>(x);
    select_build_v_kernel<<<1, 1024>>>(mn, xdec);

    cudaFuncSetAttribute(gemm_mma_kernel, cudaFuncAttributeMaxDynamicSharedMemorySize, GEMM_SMEM);
    dim3 grid((MROWS + BM - 1) / BM, DMODEL / BN);   // (17, 16)
    gemm_mma_kernel<<<grid, 512, GEMM_SMEM>>>(out);
}

// round 16
// speedup vs baseline: 1.8502x; 1.7980x over previous
#include <cuda_runtime.h>
#include <cuda_fp16.h>
#include <cstdint>
#include <cstddef>

#define DFF     11008
#define DMODEL  4096
#define SEQ     2048
#define MROWS   2049
#define KTOK    2201
#define KCORE   2201
#define NSPLIT  2201
#define TARGET  4403
#define NREM    (DFF - NSPLIT)

// ---- GEMM tiling (fp16, BK=64 -> 128B rows, identical layout to R9) ----
#define BM 128
#define BN 256
#define BK 64
#define KTILES (DFF / BK)          // 172
#define STAGES 4
#define ASTG  (BM * BK * 2)        // 16384
#define BSTG  (BN * BK * 2)        // 32768
#define STGB  (ASTG + BSTG)        // 49152
#define GEMM_SMEM (STAGES * STGB)  // 196608, 1 CTA/SM

// ---------------- device scratch ----------------
__device__ __align__(16) __half g_Xh[(size_t)SEQ * DFF];     // fp16(rna) X
__device__ __align__(16) __half g_Wh[(size_t)DMODEL * DFF];  // fp16(rna) W
__device__ __align__(16) __half g_vh[DFF];
__device__ __align__(16) __half g_zeroh[DFF];                // stays zero
__device__ int g_counts[DFF];

// ---------------- helpers ----------------
__device__ __forceinline__ unsigned fkey(float f) {
    unsigned u = __float_as_uint(f);
    return (u & 0x80000000u) ? ~u : (u | 0x80000000u);
}
__device__ __forceinline__ uint32_t smem_u32(const void* p) {
    uint32_t a;
    asm("{ .reg .u64 t; cvta.to.shared.u64 t, %1; cvt.u32.u64 %0, t; }" : "=r"(a) : "l"(p));
    return a;
}
__device__ __forceinline__ void cp16(uint32_t dst, const void* src) {
    asm volatile("cp.async.cg.shared.global [%0], [%1], 16;\n" :: "r"(dst), "l"(src) : "memory");
}
#define CP_COMMIT() asm volatile("cp.async.commit_group;\n" ::: "memory")
#define CP_WAIT(N)  asm volatile("cp.async.wait_group %0;\n" :: "n"(N) : "memory")

// m16n8k16 fp16 mma, fp32 accum
__device__ __forceinline__ void mma_f16(float c[4],
    unsigned a0, unsigned a1, unsigned a2, unsigned a3, unsigned b0, unsigned b1)
{
    asm volatile(
        "mma.sync.aligned.m16n8k16.row.col.f32.f16.f16.f32 "
        "{%0,%1,%2,%3}, {%4,%5,%6,%7}, {%8,%9}, {%0,%1,%2,%3};\n"
        : "+f"(c[0]), "+f"(c[1]), "+f"(c[2]), "+f"(c[3])
        : "r"(a0), "r"(a1), "r"(a2), "r"(a3), "r"(b0), "r"(b1));
}
__device__ __forceinline__ unsigned ldsw(uint32_t base, int r, int c) {
    unsigned v;
    uint32_t a = base + (uint32_t)(r * 128) + (uint32_t)((c * 4) ^ ((r & 7) << 4));
    asm("ld.shared.b32 %0, [%1];" : "=r"(v) : "r"(a));
    return v;
}

// ---------------- kernel A: convert W fp32->fp16(rna) + zero scratch ---------
__global__ void convertW_zero_kernel(const float4* __restrict__ src) {
    int i = blockIdx.x * blockDim.x + threadIdx.x;
    if (i < DFF) { g_counts[i] = 0; g_vh[i] = __float2half_rn(0.0f); }
    if (i < (DMODEL * DFF) / 4) {
        float4 v = src[i];
        __half2* dst = (__half2*)g_Wh + 2 * (size_t)i;
        dst[0] = __floats2half2_rn(v.x, v.y);
        dst[1] = __floats2half2_rn(v.z, v.w);
    }
}

// ---------------- kernel B: per-token top-KTOK (register radix select) --------
// Also writes the fp16(rna) row into g_Xh (fused convert).
#define NITER (DFF / 256)   // 43
__global__ __launch_bounds__(256) void topk_count_kernel(const float* __restrict__ x) {
    const float* row = x + (size_t)blockIdx.x * DFF;
    __half* grow = g_Xh + (size_t)blockIdx.x * DFF;
    const int tid = threadIdx.x;
    const int lane = tid & 31, warp = tid >> 5;
    __shared__ int s_w[8];
    __shared__ int s_base;

    unsigned key[NITER];
    #pragma unroll
    for (int j = 0; j < NITER; ++j) {
        float f = row[tid + 256 * j];
        key[j] = fkey(f);
        grow[tid + 256 * j] = __float2half_rn(f);
    }

    // bitwise bisection for T = KTOK-th largest key (exact)
    unsigned p = 0;
    for (int b = 31; b >= 0; --b) {
        unsigned cand = p | (1u << b);
        int loc = 0;
        #pragma unroll
        for (int j = 0; j < NITER; ++j) loc += (key[j] >= cand);
        #pragma unroll
        for (int o = 16; o; o >>= 1) loc += __shfl_down_sync(0xffffffffu, loc, o);
        __syncthreads();
        if (lane == 0) s_w[warp] = loc;
        __syncthreads();
        int tot = 0;
        #pragma unroll
        for (int w = 0; w < 8; ++w) tot += s_w[w];
        if (tot >= KTOK) p = cand;
    }

    // count strictly-greater and equal in one pass
    {
        int locg = 0, loce = 0;
        #pragma unroll
        for (int j = 0; j < NITER; ++j) { locg += (key[j] > p); loce += (key[j] == p); }
        int packed = (locg << 16) | loce;
        #pragma unroll
        for (int o = 16; o; o >>= 1) packed += __shfl_down_sync(0xffffffffu, packed, o);
        __syncthreads();
        if (lane == 0) s_w[warp] = packed;
        __syncthreads();
    }
    int tot = 0;
    #pragma unroll
    for (int w = 0; w < 8; ++w) tot += s_w[w];
    const int cgt = tot >> 16;
    const int ceq = tot & 0xFFFF;
    const int need = KTOK - cgt;

    #pragma unroll
    for (int j = 0; j < NITER; ++j)
        if (key[j] > p) atomicAdd(&g_counts[tid + 256 * j], 1);

    if (ceq == need) {
        // fast path: every tie is selected
        #pragma unroll
        for (int j = 0; j < NITER; ++j)
            if (key[j] == p) atomicAdd(&g_counts[tid + 256 * j], 1);
    } else {
        // ordered tie-break: first `need` by ascending index
        if (tid == 0) s_base = 0;
        __syncthreads();
        for (int j = 0; j < NITER; ++j) {
            int eq = (key[j] == p);
            unsigned bal = __ballot_sync(0xffffffffu, eq);
            if (lane == 0) s_w[warp] = __popc(bal);
            __syncthreads();
            int woff = 0;
            for (int w = 0; w < warp; ++w) woff += s_w[w];
            int t2 = 0;
            #pragma unroll
            for (int w = 0; w < 8; ++w) t2 += s_w[w];
            if (eq) {
                int r = s_base + woff + __popc(bal & ((1u << lane) - 1u));
                if (r < need) atomicAdd(&g_counts[tid + 256 * j], 1);
            }
            __syncthreads();
            if (tid == 0) s_base += t2;
            __syncthreads();
        }
    }
}

// ---------------- kernel C: core selection + union + build v ----------------
__device__ __forceinline__ int blockScanBit(int flag, int tid, unsigned* wsum, int* tot) {
    int lane = tid & 31, w = tid >> 5;
    unsigned b = __ballot_sync(0xffffffffu, flag);
    int pre = __popc(b & ((1u << lane) - 1u));
    if (lane == 0) wsum[w] = __popc(b);
    __syncthreads();
    if (w == 0) {
        int v = (int)wsum[lane];
        #pragma unroll
        for (int o = 1; o < 32; o <<= 1) {
            int n = __shfl_up_sync(0xffffffffu, v, o);
            if (lane >= o) v += n;
        }
        wsum[lane] = (unsigned)v;
    }
    __syncthreads();
    int off = w ? (int)wsum[w - 1] : 0;
    *tot = (int)wsum[31];
    int r = off + pre;
    __syncthreads();
    return r;
}

__device__ __forceinline__ int blockScanAddInc(int v, int tid, int* wsum32) {
    int lane = tid & 31, w = tid >> 5;
    #pragma unroll
    for (int o = 1; o < 32; o <<= 1) {
        int n = __shfl_up_sync(0xffffffffu, v, o);
        if (lane >= o) v += n;
    }
    if (lane == 31) wsum32[w] = v;
    __syncthreads();
    if (w == 0) {
        int s = wsum32[lane];
        #pragma unroll
        for (int o = 1; o < 32; o <<= 1) {
            int n = __shfl_up_sync(0xffffffffu, s, o);
            if (lane >= o) s += n;
        }
        wsum32[lane] = s;
    }
    __syncthreads();
    int off = w ? wsum32[w - 1] : 0;
    int r = v + off;
    __syncthreads();
    return r;
}

__global__ __launch_bounds__(1024) void select_build_v_kernel(
    const int* __restrict__ mneur, const float* __restrict__ xdec)
{
    __shared__ int hist[2049];
    __shared__ unsigned wsum[32];
    __shared__ int iwsum[32];
    __shared__ unsigned maskw[(DFF + 31) / 32];
    __shared__ int s_cstar, s_need, s_carry, s_U;

    const int tid = threadIdx.x;
    for (int i = tid; i < 2049; i += 1024) hist[i] = 0;
    for (int i = tid; i < (DFF + 31) / 32; i += 1024) maskw[i] = 0u;
    __syncthreads();

    for (int i = tid; i < DFF; i += 1024) atomicAdd(&hist[g_counts[i]], 1);
    __syncthreads();

    {
        int e0 = hist[2048 - (2 * tid)];
        int e1 = hist[2048 - (2 * tid + 1)];
        int inc = blockScanAddInc(e0 + e1, tid, iwsum);
        int P1 = inc;
        int P0 = inc - e1;
        int Pm1 = P0 - e0;
        if (P0 >= KCORE && Pm1 < KCORE) { s_cstar = 2048 - 2 * tid; s_need = KCORE - Pm1; }
        if (P1 >= KCORE && P0  < KCORE) { s_cstar = 2048 - (2 * tid + 1); s_need = KCORE - P0; }
        if (tid == 1023 && P1 < KCORE)  { s_cstar = 0; s_need = KCORE - P1; }
        if (tid == 0) s_carry = 0;
    }
    __syncthreads();

    for (int j = tid; j < NSPLIT; j += 1024) {
        int n = mneur[j];
        atomicOr(&maskw[n >> 5], 1u << (n & 31));
    }
    const int cs = s_cstar, need = s_need;
    __syncthreads();

    for (int base = 0; base < DFF; base += 1024) {
        int i = base + tid;
        int cnt = (i < DFF) ? g_counts[i] : -1;
        int eq = (cnt == cs);
        int tot;
        int pre = blockScanBit(eq, tid, wsum, &tot);
        int take = eq && (s_carry + pre) < need;
        if ((cnt > cs) || take) atomicOr(&maskw[i >> 5], 1u << (i & 31));
        __syncthreads();
        if (tid == 0) s_carry += tot;
        __syncthreads();
    }

    if (tid == 0) s_carry = 0;
    __syncthreads();
    for (int base = 0; base < DFF; base += 1024) {
        int i = base + tid;
        int fl = (i < DFF) && ((maskw[i >> 5] >> (i & 31)) & 1u);
        int tot;
        int pre = blockScanBit(fl, tid, wsum, &tot);
        if (fl) g_vh[i] = __float2half_rn(xdec[s_carry + pre]);
        __syncthreads();
        if (tid == 0) s_carry += tot;
        __syncthreads();
    }
    if (tid == 0) { s_U = s_carry; s_carry = 0; }
    __syncthreads();
    const int U = s_U;
    const int R = TARGET - U;

    for (int base = 0; base < NREM; base += 1024) {
        int j = base + tid;
        int nj = (j < NREM) ? mneur[NSPLIT + j] : 0;
        int fl = (j < NREM) && !((maskw[nj >> 5] >> (nj & 31)) & 1u);
        int tot;
        int pre = blockScanBit(fl, tid, wsum, &tot);
        int pos = s_carry + pre;
        if (fl && pos < R) g_vh[nj] = __float2half_rn(xdec[U + pos]);
        __syncthreads();
        if (tid == 0) s_carry += tot;
        __syncthreads();
    }
}

// ---------------- kernel D: FP16 mma.sync GEMM, 128x256, 512 thr, 4-stage ----
// out(2049x4096) = X'(2049x11008) @ W^T. 16 warps (4/SMSP), 64x32 warp tiles.
__global__ __launch_bounds__(512, 1) void gemm_mma_kernel(float* __restrict__ out)
{
    extern __shared__ char smem[];
    const uint32_t sb = smem_u32(smem);
    const int tid  = threadIdx.x;
    const int lane = tid & 31;
    const int warp = tid >> 5;       // 0..15
    const int gid  = lane >> 2;      // 0..7
    const int tig  = lane & 3;       // 0..3
    const int wm   = (warp & 1) * 64;        // 0,64
    const int wn   = (warp >> 1) * 32;       // 0..224
    const int m0   = blockIdx.x * BM;
    const int n0   = blockIdx.y * BN;

    // cp.async geometry: 512 threads, 6 chunks each (A:2, B:4); 16B = 8 fp16
    const int cc = tid & 7;          // 16B chunk in 128B row
    const int rb = tid >> 3;         // 0..63
    const __half* aSrc[2];
    #pragma unroll
    for (int p = 0; p < 2; ++p) {
        int m = m0 + rb + 64 * p;
        aSrc[p] = (m < SEQ) ? (g_Xh + (size_t)m * DFF + cc * 8)
                 : (m == SEQ ? (g_vh + cc * 8) : (g_zeroh + cc * 8));
    }
    const __half* bSrc = g_Wh + (size_t)(n0 + rb) * DFF + cc * 8;
    const uint32_t swo = (uint32_t)((cc * 16) ^ ((rb & 7) << 4));

    auto load_stage = [&](int s, int kt) {
        uint32_t ab = sb + s * STGB;
        uint32_t bb = ab + ASTG;
        #pragma unroll
        for (int p = 0; p < 2; ++p)
            cp16(ab + (uint32_t)((rb + 64 * p) * 128) + swo, aSrc[p] + (size_t)kt * BK);
        #pragma unroll
        for (int q = 0; q < 4; ++q)
            cp16(bb + (uint32_t)((rb + 64 * q) * 128) + swo, bSrc + (size_t)q * 64 * DFF + (size_t)kt * BK);
    };

    float acc[4][4][4];
    #pragma unroll
    for (int mt = 0; mt < 4; ++mt)
        #pragma unroll
        for (int nt = 0; nt < 4; ++nt)
            #pragma unroll
            for (int q = 0; q < 4; ++q) acc[mt][nt][q] = 0.0f;

    #pragma unroll
    for (int s = 0; s < STAGES - 1; ++s) { load_stage(s, s); CP_COMMIT(); }

    #pragma unroll 1
    for (int kt = 0; kt < KTILES; ++kt) {
        CP_WAIT(STAGES - 2);
        __syncthreads();

        if (kt + STAGES - 1 < KTILES) {
            int s = (kt + STAGES - 1) % STAGES;
            load_stage(s, kt + STAGES - 1);
        }
        CP_COMMIT();

        const uint32_t ab = sb + (kt % STAGES) * STGB;
        const uint32_t bb = ab + ASTG;

        // 4 k-steps of 16: same word offsets as the proven fp32 kernel
        #pragma unroll
        for (int ks = 0; ks < 4; ++ks) {
            const int kb = ks * 8;
            unsigned a[4][4], b[4][2];
            #pragma unroll
            for (int mt = 0; mt < 4; ++mt) {
                int r = wm + mt * 16 + gid;
                a[mt][0] = ldsw(ab, r,     kb + tig);
                a[mt][1] = ldsw(ab, r + 8, kb + tig);
                a[mt][2] = ldsw(ab, r,     kb + tig + 4);
                a[mt][3] = ldsw(ab, r + 8, kb + tig + 4);
            }
            #pragma unroll
            for (int nt = 0; nt < 4; ++nt) {
                int c = wn + nt * 8 + gid;
                b[nt][0] = ldsw(bb, c, kb + tig);
                b[nt][1] = ldsw(bb, c, kb + tig + 4);
            }
            #pragma unroll
            for (int mt = 0; mt < 4; ++mt)
                #pragma unroll
                for (int nt = 0; nt < 4; ++nt)
                    mma_f16(acc[mt][nt], a[mt][0], a[mt][1], a[mt][2], a[mt][3],
                            b[nt][0], b[nt][1]);
        }
    }

    // epilogue: plain stores with row guard
    #pragma unroll
    for (int mt = 0; mt < 4; ++mt) {
        int r0 = m0 + wm + mt * 16 + gid;
        #pragma unroll
        for (int nt = 0; nt < 4; ++nt) {
            int c = n0 + wn + nt * 8 + tig * 2;
            if (r0 < MROWS)
                *(float2*)(out + (size_t)r0 * DMODEL + c) = make_float2(acc[mt][nt][0], acc[mt][nt][1]);
            if (r0 + 8 < MROWS)
                *(float2*)(out + (size_t)(r0 + 8) * DMODEL + c) = make_float2(acc[mt][nt][2], acc[mt][nt][3]);
        }
    }
}

// ---------------- launcher ----------------
extern "C" void kernel_launch(void* const* d_in, const int* in_sizes, int n_in,
                              void* d_out, int out_size) {
    const float* x    = (const float*)d_in[0];
    const float* W    = (const float*)d_in[1];
    const float* xdec = (const float*)d_in[2];
    const int*   mn   = (const int*)d_in[3];
    float* out = (float*)d_out;

    convertW_zero_kernel<<<((DMODEL * DFF / 4) + 255) / 256, 256>>>((const float4*)W);
    topk_count_kernel<<<SEQ, 256>>>(x);
    select_build_v_kernel<<<1, 1024>>>(mn, xdec);

    cudaFuncSetAttribute(gemm_mma_kernel, cudaFuncAttributeMaxDynamicSharedMemorySize, GEMM_SMEM);
    dim3 grid((MROWS + BM - 1) / BM, DMODEL / BN);   // (17, 16)
    gemm_mma_kernel<<<grid, 512, GEMM_SMEM>>>(out);
}